// round 17
// baseline (speedup 1.0000x reference)
#include <cuda_runtime.h>
#include <cuda_bf16.h>
#include <math.h>
#include <stdint.h>

#define N_NODES 2048
#define B_BATCH 32
#define C_IN    64
#define KIO     12288                 // K*C*O = 3*64*64
#define NC      (N_NODES * C_IN)      // 131072

// ---------------------------------------------------------------------------
__device__ __forceinline__ uint32_t smem_to_u32(const void* p) {
    uint32_t a;
    asm("{ .reg .u64 t; cvta.to.shared.u64 t, %1; cvt.u32.u64 %0, t; }"
        : "=r"(a) : "l"(p));
    return a;
}

#define CP_ASYNC16(saddr, gptr) \
    asm volatile("cp.async.cg.shared.global [%0], [%1], 16;" \
                 :: "r"(saddr), "l"(gptr) : "memory")
#define CP_COMMIT() asm volatile("cp.async.commit_group;" ::: "memory")
#define CP_WAIT0()  asm volatile("cp.async.wait_group 0;" ::: "memory")

#define LDSM4(r0, r1, r2, r3, addr) \
    asm volatile("ldmatrix.sync.aligned.m8n8.x4.shared.b16 {%0,%1,%2,%3}, [%4];" \
                 : "=r"(r0), "=r"(r1), "=r"(r2), "=r"(r3) : "r"(addr))

#define MMA_BF16(c, a, b) \
    asm volatile("mma.sync.aligned.m16n8k16.row.col.f32.bf16.bf16.f32 " \
                 "{%0,%1,%2,%3}, {%4,%5,%6,%7}, {%8,%9}, {%0,%1,%2,%3};" \
                 : "+f"((c)[0]), "+f"((c)[1]), "+f"((c)[2]), "+f"((c)[3]) \
                 : "r"((a)[0]), "r"((a)[1]), "r"((a)[2]), "r"((a)[3]), \
                   "r"((b)[0]), "r"((b)[1]))

// ---------------------------------------------------------------------------
// scratch (device globals; no allocation allowed)
// ---------------------------------------------------------------------------
__device__ float g_S0[N_NODES * N_NODES];                       // fp32 (blend input)
__device__ float g_Y1[N_NODES * N_NODES];                       // [n][b*64+c]
__device__ float g_Y2[N_NODES * N_NODES];
__device__ float g_XT[N_NODES * N_NODES];                       // fp32 x^T [j][m]
__device__ __nv_bfloat16 g_S0h[N_NODES * N_NODES], g_S0l[N_NODES * N_NODES];
__device__ __nv_bfloat16 g_adjh[N_NODES * N_NODES], g_adjl[N_NODES * N_NODES];
__device__ __nv_bfloat16 g_saw_h[N_NODES * 4096],  g_saw_l[N_NODES * 4096];
__device__ __nv_bfloat16 g_S_h [N_NODES * N_NODES], g_S_l [N_NODES * N_NODES];
__device__ __nv_bfloat16 g_Y1Th[N_NODES * N_NODES], g_Y1Tl[N_NODES * N_NODES];
__device__ __nv_bfloat16 g_X_h [N_NODES * N_NODES], g_X_l [N_NODES * N_NODES];
__device__ float g_W [N_NODES * KIO];
__device__ float g_bias[N_NODES * 64];

__device__ __forceinline__ void split2(float a, __nv_bfloat16& h, __nv_bfloat16& l) {
    h = __float2bfloat16(a);
    l = __float2bfloat16(a - __bfloat162float(h));
}

// ---------------------------------------------------------------------------
// streams/events for fork-join overlap (host objects; created once pre-main)
// ---------------------------------------------------------------------------
struct OverlapRes {
    cudaStream_t s1, s2;
    cudaEvent_t eRoot, eSaw, eC, eW, eY1, eP;
    OverlapRes() {
        cudaStreamCreateWithFlags(&s1, cudaStreamNonBlocking);
        cudaStreamCreateWithFlags(&s2, cudaStreamNonBlocking);
        cudaEventCreateWithFlags(&eRoot, cudaEventDisableTiming);
        cudaEventCreateWithFlags(&eSaw, cudaEventDisableTiming);
        cudaEventCreateWithFlags(&eC,   cudaEventDisableTiming);
        cudaEventCreateWithFlags(&eW,   cudaEventDisableTiming);
        cudaEventCreateWithFlags(&eY1,  cudaEventDisableTiming);
        cudaEventCreateWithFlags(&eP,   cudaEventDisableTiming);
    }
};
static OverlapRes g_ov;

// ============================================================================
// Kernel 1: S0 = softmax(relu(E E^T), rows), emitting fp32 + bf16 hi/lo.
// ============================================================================
__global__ __launch_bounds__(256) void k_supports(const float* __restrict__ E,
                                                  float* __restrict__ S0,
                                                  __nv_bfloat16* __restrict__ S0h,
                                                  __nv_bfloat16* __restrict__ S0l)
{
    const int n = blockIdx.x;
    const int t = threadIdx.x;
    __shared__ float en[16];
    __shared__ float red[256];
    if (t < 16) en[t] = E[n * 16 + t];
    __syncthreads();

    float v[8];
    float mx = -1e30f;
#pragma unroll
    for (int r = 0; r < 8; r++) {
        const int m = r * 256 + t;
        const float4* em = reinterpret_cast<const float4*>(E + m * 16);
        float4 a0 = em[0], a1 = em[1], a2 = em[2], a3 = em[3];
        float d = a0.x*en[0] + a0.y*en[1] + a0.z*en[2] + a0.w*en[3]
                + a1.x*en[4] + a1.y*en[5] + a1.z*en[6] + a1.w*en[7]
                + a2.x*en[8] + a2.y*en[9] + a2.z*en[10] + a2.w*en[11]
                + a3.x*en[12] + a3.y*en[13] + a3.z*en[14] + a3.w*en[15];
        d = fmaxf(d, 0.0f);
        v[r] = d;
        mx = fmaxf(mx, d);
    }
    red[t] = mx; __syncthreads();
    for (int s = 128; s > 0; s >>= 1) {
        if (t < s) red[t] = fmaxf(red[t], red[t + s]);
        __syncthreads();
    }
    mx = red[0];
    __syncthreads();
    float sum = 0.0f;
#pragma unroll
    for (int r = 0; r < 8; r++) { v[r] = expf(v[r] - mx); sum += v[r]; }
    red[t] = sum; __syncthreads();
    for (int s = 128; s > 0; s >>= 1) {
        if (t < s) red[t] += red[t + s];
        __syncthreads();
    }
    const float inv = 1.0f / red[0];
#pragma unroll
    for (int r = 0; r < 8; r++) {
        const float a = v[r] * inv;
        const size_t off = (size_t)n * N_NODES + r * 256 + t;
        S0[off] = a;
        __nv_bfloat16 h, l; split2(a, h, l);
        S0h[off] = h; S0l[off] = l;
    }
}

// ============================================================================
// Generic split (fp32 -> bf16 hi/lo)
// ============================================================================
__global__ __launch_bounds__(256) void k_split(const float* __restrict__ src,
                                               __nv_bfloat16* __restrict__ hi,
                                               __nv_bfloat16* __restrict__ lo)
{
    const size_t e0 = ((size_t)blockIdx.x * 256 + threadIdx.x) * 4;
    float4 v = *reinterpret_cast<const float4*>(src + e0);
    __nv_bfloat16 h, l;
    split2(v.x, h, l); hi[e0+0] = h; lo[e0+0] = l;
    split2(v.y, h, l); hi[e0+1] = h; lo[e0+1] = l;
    split2(v.z, h, l); hi[e0+2] = h; lo[e0+2] = l;
    split2(v.w, h, l); hi[e0+3] = h; lo[e0+3] = l;
}

// x[b][m][c] -> X[j=b*64+c][m]  (bf16 hi/lo + fp32 XT)
__global__ __launch_bounds__(256) void k_split_x(const float* __restrict__ x)
{
    __shared__ float t[64][65];
    const int b = blockIdx.y;
    const int m0 = blockIdx.x * 64;
    const int tid = threadIdx.x;
#pragma unroll
    for (int p = 0; p < 16; p++) {
        const int e = p * 256 + tid;
        const int r = e >> 6, c = e & 63;
        t[r][c] = x[(size_t)b * NC + (size_t)(m0 + r) * 64 + c];
    }
    __syncthreads();
#pragma unroll
    for (int p = 0; p < 16; p++) {
        const int e = p * 256 + tid;
        const int r = e >> 6, c = e & 63;
        float a = t[c][r];
        const size_t off = (size_t)(b * 64 + r) * 2048 + m0 + c;
        g_XT[off] = a;
        __nv_bfloat16 h, l; split2(a, h, l);
        g_X_h[off] = h;
        g_X_l[off] = l;
    }
}

// ============================================================================
// HMMA (mma.sync bf16) split GEMM: D[i][j] = sum_k A[i][k] * B[j][k]
// 256x128 CTA tile, 512 threads = 16 warps (4m x 4n), warp tile 64x32,
// K-chunk 64, double-buffered cp.async (2 x 96KB smem).
// 3-term split, order hh -> hl -> lh (A-fragment registers reused for a_lo).
// Prefetch of chunk c+1 spread over the 4 ks sub-iterations (3/thread/ks).
// MODE 1: piecewise A (S0 | adj); sigmoid blend -> Sh/Sl (bf16 hi/lo)
// MODE 3: outF = 2*D - XT^T   (e_adj carries fp32 XT [j][m])
// MODE 4: outF = D fp32  AND  oH/oL = transposed bf16 hi/lo of D
// smem buffer layout: A_h 32KB @0 | A_l @32768 | B_h 16KB @65536 | B_l @81920
// ============================================================================
#define GEMM_BUF   98304
#define GEMM_SMEM_SZ (2 * GEMM_BUF)
#define GEMM_THREADS 512

template<int MODE>
__global__ __launch_bounds__(GEMM_THREADS, 1)
void k_gemm(const __nv_bfloat16* __restrict__ Ah, const __nv_bfloat16* __restrict__ Al,
            const __nv_bfloat16* __restrict__ A2h, const __nv_bfloat16* __restrict__ A2l,
            const __nv_bfloat16* __restrict__ Bh, const __nv_bfloat16* __restrict__ Bl,
            float* __restrict__ outF,
            __nv_bfloat16* __restrict__ oH, __nv_bfloat16* __restrict__ oL,
            int ktot, int lda, int ldb,
            const float* __restrict__ e_adj, const float* __restrict__ e_s0)
{
    extern __shared__ char smem[];
    const uint32_t sb = smem_to_u32(smem);
    const int tid = threadIdx.x;
    const int wid = tid >> 5;
    const int lane = tid & 31;
    const int wm = wid >> 2;          // 0..3  (m offset 64 each)
    const int wn = wid & 3;           // 0..3  (n offset 32 each)
    const int iBase = blockIdx.y * 256;
    const int jBase = blockIdx.x * 128;

    float acc[4][4][4];
#pragma unroll
    for (int mt = 0; mt < 4; mt++)
#pragma unroll
        for (int nt = 0; nt < 4; nt++)
#pragma unroll
            for (int q = 0; q < 4; q++) acc[mt][nt][q] = 0.0f;

    const int nchunk = ktot >> 6;

    // issue one quarter (3 cp.async per thread) of chunk cch's loads
    auto load_part = [&](int cch, uint32_t bufbase, int part) {
        const int kt = cch << 6;
        const __nv_bfloat16* ah = Ah;
        const __nv_bfloat16* al = Al;
        int ka = kt;
        if (MODE == 1 && kt >= 2048) { ah = A2h; al = A2l; ka = kt - 2048; }
#pragma unroll
        for (int q = 0; q < 3; q++) {
            const int idx = part * 3 + q;
            if (idx < 8) {                        // A tiles (hi: 0..3, lo: 4..7)
                const int t4 = idx >> 2, p = idx & 3;
                const __nv_bfloat16* g = t4 ? al : ah;
                const uint32_t soff = bufbase + t4 * 32768;
                const int u = tid + p * 512;
                const int r = u >> 3, c16 = u & 7;
                const __nv_bfloat16* gp = g + (size_t)(iBase + r) * lda + ka + c16 * 8;
                CP_ASYNC16(soff + (r * 128 + ((c16 * 16) ^ ((r & 7) << 4))), gp);
            } else {                              // B tiles (hi: 8..9, lo: 10..11)
                const int t4 = (idx - 8) >> 1, p = (idx - 8) & 1;
                const __nv_bfloat16* g = t4 ? Bl : Bh;
                const uint32_t soff = bufbase + 65536 + t4 * 16384;
                const int u = tid + p * 512;
                const int r = u >> 3, c16 = u & 7;
                const __nv_bfloat16* gp = g + (size_t)(jBase + r) * ldb + kt + c16 * 8;
                CP_ASYNC16(soff + (r * 128 + ((c16 * 16) ^ ((r & 7) << 4))), gp);
            }
        }
    };

    // prologue: full chunk 0
#pragma unroll
    for (int part = 0; part < 4; part++) load_part(0, sb, part);
    CP_COMMIT();

    // per-thread fragment address components
    const int mrow0 = wm * 64 + (lane & 15);
    const int aKsel = (lane >> 4) * 16;
    const int brow0 = wn * 32 + ((lane >> 4) << 3) + (lane & 7);
    const int bKsel = ((lane >> 3) & 1) * 16;

    for (int cch = 0; cch < nchunk; cch++) {
        CP_WAIT0();
        __syncthreads();
        const uint32_t tb = sb + (cch & 1) * GEMM_BUF;
        const uint32_t nb = sb + ((cch + 1) & 1) * GEMM_BUF;
        const bool pf = (cch + 1 < nchunk);
#pragma unroll
        for (int ks = 0; ks < 4; ks++) {
            if (pf) load_part(cch + 1, nb, ks);
            uint32_t a[4][4];
            const int kbyA = ks * 32 + aKsel;
            const int kbyB = ks * 32 + bKsel;
            // A hi fragments
#pragma unroll
            for (int mt = 0; mt < 4; mt++) {
                const int row = mrow0 + mt * 16;
                const uint32_t ad = tb + row * 128 + (kbyA ^ ((row & 7) << 4));
                LDSM4(a[mt][0], a[mt][1], a[mt][2], a[mt][3], ad);
            }
            // B hi fragments (warp's 32-wide slab: 2 LDSM4)
            uint32_t bh[4][2], bl[4][2];
#pragma unroll
            for (int np = 0; np < 2; np++) {
                const int row = brow0 + np * 16;
                const uint32_t bd = tb + 65536 + row * 128 + (kbyB ^ ((row & 7) << 4));
                uint32_t t0, t1, t2, t3;
                LDSM4(t0, t1, t2, t3, bd);
                bh[2*np][0] = t0; bh[2*np][1] = t1;
                bh[2*np+1][0] = t2; bh[2*np+1][1] = t3;
            }
            // term hh
#pragma unroll
            for (int mt = 0; mt < 4; mt++)
#pragma unroll
                for (int nt = 0; nt < 4; nt++)
                    MMA_BF16(acc[mt][nt], a[mt], bh[nt]);
            // B lo fragments
#pragma unroll
            for (int np = 0; np < 2; np++) {
                const int row = brow0 + np * 16;
                const uint32_t bd = tb + 81920 + row * 128 + (kbyB ^ ((row & 7) << 4));
                uint32_t t0, t1, t2, t3;
                LDSM4(t0, t1, t2, t3, bd);
                bl[2*np][0] = t0; bl[2*np][1] = t1;
                bl[2*np+1][0] = t2; bl[2*np+1][1] = t3;
            }
            // term hl
#pragma unroll
            for (int mt = 0; mt < 4; mt++)
#pragma unroll
                for (int nt = 0; nt < 4; nt++)
                    MMA_BF16(acc[mt][nt], a[mt], bl[nt]);
            // A lo fragments (reuse a regs)
#pragma unroll
            for (int mt = 0; mt < 4; mt++) {
                const int row = mrow0 + mt * 16;
                const uint32_t ad = tb + 32768 + row * 128 + (kbyA ^ ((row & 7) << 4));
                LDSM4(a[mt][0], a[mt][1], a[mt][2], a[mt][3], ad);
            }
            // term lh
#pragma unroll
            for (int mt = 0; mt < 4; mt++)
#pragma unroll
                for (int nt = 0; nt < 4; nt++)
                    MMA_BF16(acc[mt][nt], a[mt], bh[nt]);
        }
        if (pf) CP_COMMIT();
    }

    // ---- epilogue ----
    const int r0 = lane >> 2;
    const int c0 = (lane & 3) * 2;

    if (MODE == 3) {
#pragma unroll
        for (int mt = 0; mt < 4; mt++)
#pragma unroll
            for (int nt = 0; nt < 4; nt++) {
                const int j = jBase + wn * 32 + nt * 8 + c0;
#pragma unroll
                for (int half = 0; half < 2; half++) {
                    const int i = iBase + wm * 64 + mt * 16 + r0 + half * 8;
                    float2 o;
                    o.x = 2.0f * acc[mt][nt][half * 2 + 0] - e_adj[(size_t)j * 2048 + i];
                    o.y = 2.0f * acc[mt][nt][half * 2 + 1] - e_adj[(size_t)(j + 1) * 2048 + i];
                    *reinterpret_cast<float2*>(outF + (size_t)i * 2048 + j) = o;
                }
            }
    } else if (MODE == 1) {
#pragma unroll
        for (int mt = 0; mt < 4; mt++)
#pragma unroll
            for (int nt = 0; nt < 4; nt++) {
                const int j = jBase + wn * 32 + nt * 8 + c0;
#pragma unroll
                for (int half = 0; half < 2; half++) {
                    const int i = iBase + wm * 64 + mt * 16 + r0 + half * 8;
                    const float v0 = acc[mt][nt][half * 2 + 0];
                    const float v1 = acc[mt][nt][half * 2 + 1];
                    const size_t off = (size_t)i * 2048 + j;
                    float2 aj = *reinterpret_cast<const float2*>(e_adj + off);
                    float2 s0 = *reinterpret_cast<const float2*>(e_s0 + off);
                    float s, b0, b1;
                    s = 1.0f / (1.0f + expf(-v0)); b0 = s0.x + s * (aj.x - s0.x);
                    s = 1.0f / (1.0f + expf(-v1)); b1 = s0.y + s * (aj.y - s0.y);
                    __nv_bfloat16 h0, l0, h1, l1;
                    split2(b0, h0, l0); split2(b1, h1, l1);
                    *reinterpret_cast<__nv_bfloat162*>(oH + off) = __nv_bfloat162(h0, h1);
                    *reinterpret_cast<__nv_bfloat162*>(oL + off) = __nv_bfloat162(l0, l1);
                }
            }
    } else {
        // MODE 4: fp32 out from regs, then transposed bf16 hi/lo via smem stage.
#pragma unroll
        for (int mt = 0; mt < 4; mt++)
#pragma unroll
            for (int nt = 0; nt < 4; nt++) {
                const int j = jBase + wn * 32 + nt * 8 + c0;
#pragma unroll
                for (int half = 0; half < 2; half++) {
                    const int i = iBase + wm * 64 + mt * 16 + r0 + half * 8;
                    float2 o;
                    o.x = acc[mt][nt][half * 2 + 0];
                    o.y = acc[mt][nt][half * 2 + 1];
                    *reinterpret_cast<float2*>(outF + (size_t)i * 2048 + j) = o;
                }
            }
        __syncthreads();   // all warps done with MMA smem buffers
        float* sf = reinterpret_cast<float*>(smem);
#pragma unroll
        for (int mt = 0; mt < 4; mt++)
#pragma unroll
            for (int nt = 0; nt < 4; nt++) {
                const int lc = wn * 32 + nt * 8 + c0;
#pragma unroll
                for (int half = 0; half < 2; half++) {
                    const int li = wm * 64 + mt * 16 + r0 + half * 8;
                    sf[li * 129 + lc]     = acc[mt][nt][half * 2 + 0];
                    sf[li * 129 + lc + 1] = acc[mt][nt][half * 2 + 1];
                }
            }
        __syncthreads();
        // transposed writes: oT[j][i] = D[i][j], 128 j-rows x 256 i (pairs)
#pragma unroll
        for (int p = 0; p < 32; p++) {
            const int e2 = p * 512 + tid;
            const int j = e2 >> 7;             // 0..127
            const int i2 = (e2 & 127) * 2;     // 0..254
            float v0 = sf[i2 * 129 + j];
            float v1 = sf[(i2 + 1) * 129 + j];
            __nv_bfloat16 h0, l0, h1, l1;
            split2(v0, h0, l0); split2(v1, h1, l1);
            const size_t off = (size_t)(jBase + j) * 2048 + iBase + i2;
            *reinterpret_cast<__nv_bfloat162*>(oH + off) = __nv_bfloat162(h0, h1);
            *reinterpret_cast<__nv_bfloat162*>(oL + off) = __nv_bfloat162(l0, l1);
        }
    }
}

// ============================================================================
// Kernel: W[n][j] = sum_d E[n][d] * Wp[d][j]
// ============================================================================
__global__ __launch_bounds__(256) void k_weights(const float* __restrict__ E,
                                                 const float* __restrict__ Wp,
                                                 float* __restrict__ W)
{
    __shared__ float wp[16][256];
    __shared__ float es[128 * 16];
    const int t = threadIdx.x;
    const int jBase = blockIdx.x * 256;
    const int nBase = blockIdx.y * 128;
#pragma unroll
    for (int d = 0; d < 16; d++) wp[d][t] = Wp[d * KIO + jBase + t];
    for (int i = t; i < 128 * 16; i += 256) es[i] = E[nBase * 16 + i];
    __syncthreads();
    for (int n = 0; n < 128; n++) {
        float acc = 0.0f;
#pragma unroll
        for (int d = 0; d < 16; d++) acc = fmaf(es[n * 16 + d], wp[d][t], acc);
        W[(size_t)(nBase + n) * KIO + jBase + t] = acc;
    }
}

__global__ __launch_bounds__(256) void k_bias(const float* __restrict__ E,
                                              const float* __restrict__ bp,
                                              float* __restrict__ bias)
{
    const int idx = blockIdx.x * 256 + threadIdx.x;
    const int n = idx >> 6, o = idx & 63;
    float acc = 0.0f;
#pragma unroll
    for (int d = 0; d < 16; d++) acc = fmaf(E[n * 16 + d], bp[d * 64 + o], acc);
    bias[idx] = acc;
}

// ============================================================================
// Final, stage 1 (overlapped with Y2 GEMM):
// out[b][n][o] = bias[n][o] + sum_{ki<128} [x | Y1][b][ki] * W[n][ki][o]
// ============================================================================
__global__ __launch_bounds__(256) void k_final_partial(const float* __restrict__ x,
                                                       const float* __restrict__ bias,
                                                       float* __restrict__ out)
{
    const int oh = blockIdx.x;
    const int n = blockIdx.y;
    __shared__ float Ag[32][128];
    __shared__ float Wn[128][32];
    const int t = threadIdx.x;

    for (int idx = t; idx < 32 * 128; idx += 256) {
        const int b = idx >> 7, ki = idx & 127;
        float v;
        if (ki < 64) v = x[(size_t)b * NC + n * 64 + ki];
        else         v = g_Y1[(size_t)n * 2048 + b * 64 + (ki - 64)];
        Ag[b][ki] = v;
    }
    for (int idx = t; idx < 128 * 32; idx += 256) {
        const int ki = idx >> 5, o = idx & 31;
        Wn[ki][o] = g_W[(size_t)n * KIO + ki * 64 + oh * 32 + o];
    }
    __syncthreads();

    const int tx = t & 15, ty = t >> 4;
    const int b0 = ty * 2, o0 = tx * 2;
    float a00 = 0.f, a01 = 0.f, a10 = 0.f, a11 = 0.f;
#pragma unroll 4
    for (int ki = 0; ki < 128; ki++) {
        const float x0 = Ag[b0][ki];
        const float x1 = Ag[b0 + 1][ki];
        const float2 w = *reinterpret_cast<const float2*>(&Wn[ki][o0]);
        a00 = fmaf(x0, w.x, a00); a01 = fmaf(x0, w.y, a01);
        a10 = fmaf(x1, w.x, a10); a11 = fmaf(x1, w.y, a11);
    }
    const float bo0 = bias[n * 64 + oh * 32 + o0];
    const float bo1 = bias[n * 64 + oh * 32 + o0 + 1];
    const size_t base0 = (size_t)b0 * NC + n * 64 + oh * 32 + o0;
    const size_t base1 = (size_t)(b0 + 1) * NC + n * 64 + oh * 32 + o0;
    out[base0]     = a00 + bo0;
    out[base0 + 1] = a01 + bo1;
    out[base1]     = a10 + bo0;
    out[base1 + 1] = a11 + bo1;
}

// ============================================================================
// Final, stage 2: out += sum_{ki<64} Y2[b][ki] * W3[n][ki][o]
// ============================================================================
__global__ __launch_bounds__(256) void k_final_add(float* __restrict__ out)
{
    const int oh = blockIdx.x;
    const int n = blockIdx.y;
    __shared__ float Ag[32][64];
    __shared__ float Wn[64][32];
    const int t = threadIdx.x;

    for (int idx = t; idx < 32 * 64; idx += 256) {
        const int b = idx >> 6, ki = idx & 63;
        Ag[b][ki] = g_Y2[(size_t)n * 2048 + b * 64 + ki];
    }
    for (int idx = t; idx < 64 * 32; idx += 256) {
        const int ki = idx >> 5, o = idx & 31;
        Wn[ki][o] = g_W[(size_t)n * KIO + (128 + ki) * 64 + oh * 32 + o];
    }
    __syncthreads();

    const int tx = t & 15, ty = t >> 4;
    const int b0 = ty * 2, o0 = tx * 2;
    float a00 = 0.f, a01 = 0.f, a10 = 0.f, a11 = 0.f;
#pragma unroll 4
    for (int ki = 0; ki < 64; ki++) {
        const float x0 = Ag[b0][ki];
        const float x1 = Ag[b0 + 1][ki];
        const float2 w = *reinterpret_cast<const float2*>(&Wn[ki][o0]);
        a00 = fmaf(x0, w.x, a00); a01 = fmaf(x0, w.y, a01);
        a10 = fmaf(x1, w.x, a10); a11 = fmaf(x1, w.y, a11);
    }
    const size_t base0 = (size_t)b0 * NC + n * 64 + oh * 32 + o0;
    const size_t base1 = (size_t)(b0 + 1) * NC + n * 64 + oh * 32 + o0;
    out[base0]     += a00;
    out[base0 + 1] += a01;
    out[base1]     += a10;
    out[base1 + 1] += a11;
}

// ============================================================================
extern "C" void kernel_launch(void* const* d_in, const int* in_sizes, int n_in,
                              void* d_out, int out_size)
{
    const float* x   = (const float*)d_in[0];
    const float* E   = (const float*)d_in[1];
    const float* adj = (const float*)d_in[2];
    const float* Wp  = (const float*)d_in[3];
    const float* bp  = (const float*)d_in[4];
    const float* saW = (const float*)d_in[5];
    float* out = (float*)d_out;

    float *S0, *Y1, *Y2, *XT, *W, *bias;
    cudaGetSymbolAddress((void**)&S0, g_S0);
    cudaGetSymbolAddress((void**)&Y1, g_Y1);
    cudaGetSymbolAddress((void**)&Y2, g_Y2);
    cudaGetSymbolAddress((void**)&XT, g_XT);
    cudaGetSymbolAddress((void**)&W,  g_W);
    cudaGetSymbolAddress((void**)&bias, g_bias);
    __nv_bfloat16 *s0h, *s0l, *adjh, *adjl, *sawh, *sawl;
    __nv_bfloat16 *Sh, *Sl, *Y1Th, *Y1Tl, *Xh, *Xl;
    cudaGetSymbolAddress((void**)&s0h, g_S0h);
    cudaGetSymbolAddress((void**)&s0l, g_S0l);
    cudaGetSymbolAddress((void**)&adjh, g_adjh);
    cudaGetSymbolAddress((void**)&adjl, g_adjl);
    cudaGetSymbolAddress((void**)&sawh, g_saw_h);
    cudaGetSymbolAddress((void**)&sawl, g_saw_l);
    cudaGetSymbolAddress((void**)&Sh,  g_S_h);
    cudaGetSymbolAddress((void**)&Sl,  g_S_l);
    cudaGetSymbolAddress((void**)&Y1Th, g_Y1Th);
    cudaGetSymbolAddress((void**)&Y1Tl, g_Y1Tl);
    cudaGetSymbolAddress((void**)&Xh,  g_X_h);
    cudaGetSymbolAddress((void**)&Xl,  g_X_l);

    cudaFuncSetAttribute(k_gemm<1>, cudaFuncAttributeMaxDynamicSharedMemorySize, GEMM_SMEM_SZ);
    cudaFuncSetAttribute(k_gemm<3>, cudaFuncAttributeMaxDynamicSharedMemorySize, GEMM_SMEM_SZ);
    cudaFuncSetAttribute(k_gemm<4>, cudaFuncAttributeMaxDynamicSharedMemorySize, GEMM_SMEM_SZ);

    // ---- fork ----
    cudaEventRecord(g_ov.eRoot, 0);
    cudaStreamWaitEvent(g_ov.s1, g_ov.eRoot, 0);
    cudaStreamWaitEvent(g_ov.s2, g_ov.eRoot, 0);

    // branch s1: saW split -> weights -> bias
    k_split<<<(2048 * 4096) / 1024, 256, 0, g_ov.s1>>>(saW, sawh, sawl);
    cudaEventRecord(g_ov.eSaw, g_ov.s1);
    k_weights<<<dim3(KIO / 256, N_NODES / 128), 256, 0, g_ov.s1>>>(E, Wp, W);
    k_bias<<<(N_NODES * 64) / 256, 256, 0, g_ov.s1>>>(E, bp, bias);
    cudaEventRecord(g_ov.eW, g_ov.s1);

    // branch s2: adj split -> x transpose/split
    k_split<<<(2048 * 2048) / 1024, 256, 0, g_ov.s2>>>(adj, adjh, adjl);
    k_split_x<<<dim3(32, 32), 256, 0, g_ov.s2>>>(x);
    cudaEventRecord(g_ov.eC, g_ov.s2);

    // main chain
    k_supports<<<N_NODES, 256>>>(E, S0, s0h, s0l);
    cudaStreamWaitEvent(0, g_ov.eSaw, 0);
    cudaStreamWaitEvent(0, g_ov.eC, 0);

    // attn: A = [S0 | adj] (piecewise), B = saW; blend epilogue -> Sh/Sl
    k_gemm<1><<<dim3(16, 8), GEMM_THREADS, GEMM_SMEM_SZ>>>(
        s0h, s0l, adjh, adjl, sawh, sawl,
        nullptr, Sh, Sl,
        4096, 2048, 4096, adj, S0);

    // Y1 = S @ X  (fp32 out + fused transposed bf16 split)
    k_gemm<4><<<dim3(16, 8), GEMM_THREADS, GEMM_SMEM_SZ>>>(
        Sh, Sl, nullptr, nullptr, Xh, Xl,
        Y1, Y1Th, Y1Tl,
        2048, 2048, 2048, nullptr, nullptr);
    cudaEventRecord(g_ov.eY1, 0);

    // overlapped with Y2: partial final (bias + x*W1 + Y1*W2)
    cudaStreamWaitEvent(g_ov.s1, g_ov.eY1, 0);   // s1 already has W/bias done
    k_final_partial<<<dim3(2, N_NODES), 256, 0, g_ov.s1>>>(x, bias, out);
    cudaEventRecord(g_ov.eP, g_ov.s1);

    // Y2 = 2 * S @ Y1 - x   (MODE 3; e_adj carries XT)
    k_gemm<3><<<dim3(16, 8), GEMM_THREADS, GEMM_SMEM_SZ>>>(
        Sh, Sl, nullptr, nullptr, Y1Th, Y1Tl,
        Y2, nullptr, nullptr,
        2048, 2048, 2048, XT, nullptr);

    // join partial-final, then add Y2 contribution
    cudaStreamWaitEvent(0, g_ov.eP, 0);
    k_final_add<<<dim3(2, N_NODES), 256>>>(out);
}